// round 14
// baseline (speedup 1.0000x reference)
#include <cuda_runtime.h>
#include <cuda_fp16.h>
#include <cstdint>
#include <math.h>
#include <math_constants.h>

#define SEQ   128
#define BATCH 32
#define EMB   32
#define HID   16
#define VOCAB 32000
#define VPAD  32768        // padded vocab (pad rows contribute 0 to sum-exp)
#define CIN   48           // EMB + HID

#define VSPLIT   16        // p1 blocks per timestep (each covers 2048 vocab)
#define P2_TILES 32        // p2 blocks per timestep (each covers 1024 vocab)
#define PREP_BLOCKS 128    // VPAD / 256
#define LOG2E 1.4426950408889634f

// Scratch (no allocations allowed)
__device__ float  g_H[SEQ * BATCH * HID];          // fp32 h for p2
__device__ __half g_Hhf[SEQ * BATCH * HID];        // fp16 h * log2e for p1 MMA
__device__ __half g_Whf[VPAD * HID];               // fp16 W_ho (pad rows = 0)
__device__ float  g_b2[VPAD];                      // b_ho * log2e (pad = -2000)
__device__ float  g_partS[SEQ * VSPLIT * BATCH];

// ---- packed f32x2 helpers ---------------------------------------------------
__device__ __forceinline__ void ffma2(unsigned long long& d,
                                      unsigned long long a,
                                      unsigned long long b) {
    asm("fma.rn.f32x2 %0, %1, %2, %0;" : "+l"(d) : "l"(a), "l"(b));
}
__device__ __forceinline__ float hsum2(unsigned long long v) {
    float lo, hi;
    asm("mov.b64 {%0, %1}, %2;" : "=f"(lo), "=f"(hi) : "l"(v));
    return lo + hi;
}
__device__ __forceinline__ unsigned long long packf2(float lo, float hi) {
    unsigned long long d;
    asm("mov.b64 %0, {%1, %2};" : "=l"(d) : "f"(lo), "f"(hi));
    return d;
}
__device__ __forceinline__ float ex2(float x) {
    float r;
    asm("ex2.approx.f32 %0, %1;" : "=f"(r) : "f"(x));
    return r;
}
__device__ __forceinline__ unsigned int smem_u32(const void* p) {
    unsigned int a;
    asm("{ .reg .u64 t; cvta.to.shared.u64 t, %1; cvt.u32.u64 %0, t; }" : "=r"(a) : "l"(p));
    return a;
}

// mma.sync m16n8k16: D(f32) = A(f16) * B(f16) + C(f32)
__device__ __forceinline__ void mma16816(float& d0, float& d1, float& d2, float& d3,
                                         unsigned a0, unsigned a1, unsigned a2, unsigned a3,
                                         unsigned b0, unsigned b1) {
    const float z = 0.f;
    asm volatile(
        "mma.sync.aligned.m16n8k16.row.col.f32.f16.f16.f32 "
        "{%0,%1,%2,%3}, {%4,%5,%6,%7}, {%8,%9}, {%10,%11,%12,%13};"
        : "=f"(d0), "=f"(d1), "=f"(d2), "=f"(d3)
        : "r"(a0), "r"(a1), "r"(a2), "r"(a3), "r"(b0), "r"(b1),
          "f"(z), "f"(z), "f"(z), "f"(z));
}

// ---------------------------------------------------------------------------
// Kernel A: fused prep + recurrence (independent roles, one launch).
// ---------------------------------------------------------------------------
__global__ __launch_bounds__(256, 1)
void recur_prep_kernel(const int*   __restrict__ idx,
                       const float* __restrict__ h0,
                       const float* __restrict__ emb,
                       const float* __restrict__ W_ih,
                       const float* __restrict__ b_ih,
                       const float* __restrict__ W_ho,
                       const float* __restrict__ b_ho) {
    if (blockIdx.x < PREP_BLOCKS) {
        const int row = blockIdx.x * 256 + threadIdx.x;
        __half* d = g_Whf + row * HID;
        if (row < VOCAB) {
#pragma unroll
            for (int k = 0; k < HID; k++) d[k] = __float2half(W_ho[row * HID + k]);
            g_b2[row] = b_ho[row] * LOG2E;
        } else {
#pragma unroll
            for (int k = 0; k < HID; k++) d[k] = __float2half(0.f);
            g_b2[row] = -2000.f;
        }
        return;
    }
    if (threadIdx.x >= 32) return;     // recurrence uses one warp

    const int b    = blockIdx.x - PREP_BLOCKS;
    const int lane = threadIdx.x;
    const int i    = lane & 15;
    const int half = lane >> 4;

    __shared__ int   idxs[SEQ];
    __shared__ float comb[CIN];

    for (int t = lane; t < SEQ; t += 32) idxs[t] = idx[t * BATCH + b];

    float wih[24];
    const int base = half * 24;
#pragma unroll
    for (int j = 0; j < 24; j++) wih[j] = W_ih[i * CIN + base + j];
    const float bias = b_ih[i];

    __syncwarp();

    float x = emb[idxs[0] * EMB + lane];
    float h = (lane < 16) ? h0[b * HID + lane] : 0.f;

    for (int t = 0; t < SEQ; t++) {
        comb[lane] = x;
        if (lane < 16) comb[EMB + lane] = h;
        __syncwarp();

        if (t + 1 < SEQ) x = emb[idxs[t + 1] * EMB + lane];

        float a0 = 0.f, a1 = 0.f, a2 = 0.f;
#pragma unroll
        for (int j = 0; j < 24; j += 3) {
            a0 += wih[j]     * comb[base + j];
            a1 += wih[j + 1] * comb[base + j + 1];
            a2 += wih[j + 2] * comb[base + j + 2];
        }
        float part = (a0 + a1) + a2;
        part += __shfl_xor_sync(0xffffffffu, part, 16);

        const float z = part + bias;
        const float e = ex2(2.f * LOG2E * z);
        const float hn = __fdividef(e - 1.f, e + 1.f);

        __syncwarp();
        if (lane < 16) {
            h = hn;
            g_H[(t * BATCH + b) * HID + i] = hn;
            g_Hhf[(t * BATCH + b) * HID + i] = __float2half(hn * LOG2E);
        }
    }
}

// ---------------------------------------------------------------------------
// Kernel B (p1 via HMMA): sum-exp of logits on the tensor pipe. Unchanged.
// ---------------------------------------------------------------------------
__global__ __launch_bounds__(256, 4)
void p1_mma() {
    const int s    = blockIdx.y;
    const int bx   = blockIdx.x;
    const int tid  = threadIdx.x;
    const int warp = tid >> 5;
    const int lane = tid & 31;

    __shared__ float rS[8][BATCH];

    const int g  = lane >> 2;
    const int c4 = (lane & 3) * 2;

    const __half* Ah = g_Hhf + s * BATCH * HID;
    const unsigned a0 = *(const unsigned*)(Ah + (g)      * HID + c4);
    const unsigned a1 = *(const unsigned*)(Ah + (g + 8)  * HID + c4);
    const unsigned a2 = *(const unsigned*)(Ah + (g)      * HID + c4 + 8);
    const unsigned a3 = *(const unsigned*)(Ah + (g + 8)  * HID + c4 + 8);
    const unsigned a4 = *(const unsigned*)(Ah + (g + 16) * HID + c4);
    const unsigned a5 = *(const unsigned*)(Ah + (g + 24) * HID + c4);
    const unsigned a6 = *(const unsigned*)(Ah + (g + 16) * HID + c4 + 8);
    const unsigned a7 = *(const unsigned*)(Ah + (g + 24) * HID + c4 + 8);

    float s0 = 0.f, s1 = 0.f, s2 = 0.f, s3 = 0.f;

    const int vwarp = bx * 2048 + warp * 256;
#pragma unroll 4
    for (int tile = 0; tile < 32; tile++) {
        const int v0 = vwarp + tile * 8;
        const __half* Bp = g_Whf + (v0 + g) * HID;
        const unsigned b0 = *(const unsigned*)(Bp + c4);
        const unsigned b1 = *(const unsigned*)(Bp + c4 + 8);
        const float2 bb = *(const float2*)(g_b2 + v0 + c4);

        float d0, d1, d2, d3, e0, e1, e2, e3;
        mma16816(d0, d1, d2, d3, a0, a1, a2, a3, b0, b1);
        mma16816(e0, e1, e2, e3, a4, a5, a6, a7, b0, b1);

        s0 += ex2(d0 + bb.x) + ex2(d1 + bb.y);
        s1 += ex2(d2 + bb.x) + ex2(d3 + bb.y);
        s2 += ex2(e0 + bb.x) + ex2(e1 + bb.y);
        s3 += ex2(e2 + bb.x) + ex2(e3 + bb.y);
    }

    s0 += __shfl_xor_sync(0xffffffffu, s0, 1); s0 += __shfl_xor_sync(0xffffffffu, s0, 2);
    s1 += __shfl_xor_sync(0xffffffffu, s1, 1); s1 += __shfl_xor_sync(0xffffffffu, s1, 2);
    s2 += __shfl_xor_sync(0xffffffffu, s2, 1); s2 += __shfl_xor_sync(0xffffffffu, s2, 2);
    s3 += __shfl_xor_sync(0xffffffffu, s3, 1); s3 += __shfl_xor_sync(0xffffffffu, s3, 2);
    if ((lane & 3) == 0) {
        rS[warp][g]      = s0;
        rS[warp][g + 8]  = s1;
        rS[warp][g + 16] = s2;
        rS[warp][g + 24] = s3;
    }
    __syncthreads();
    if (tid < BATCH) {
        float S = 0.f;
#pragma unroll
        for (int w = 0; w < 8; w++) S += rS[w][tid];
        g_partS[(s * VSPLIT + bx) * BATCH + tid] = S;
    }
}

// ---------------------------------------------------------------------------
// Kernel D (pass 2): results staged in SMEM (cheap STS.128), drained to GMEM
// by cp.async.bulk 1D TMA stores (4KB per batch row), double-buffered.
// Removes the 12-cyc STG.128 issue cost from the warp path -> fma-bound.
// ---------------------------------------------------------------------------
__global__ __launch_bounds__(256, 2)
void logits_pass2(const float* __restrict__ W_ho,
                  const float* __restrict__ b_ho,
                  float* __restrict__ out) {
    const int s   = blockIdx.y;
    const int bx  = blockIdx.x;
    const int tid = threadIdx.x;

    __shared__ ulonglong2 hs[BATCH][4];
    __shared__ float      lz[BATCH];
    __shared__ __align__(16) float obuf[2][4][1024];   // 2 buf x 4 batches x 4KB

    if (tid < 128)
        ((ulonglong2*)hs)[tid] = ((const ulonglong2*)(g_H + s * BATCH * HID))[tid];
    if (tid < 32) {
        float S = 0.f;
        const float* p = g_partS + s * VSPLIT * BATCH + tid;
#pragma unroll
        for (int t = 0; t < VSPLIT; t++) S += p[t * BATCH];
        lz[tid] = __logf(S);
    }
    __syncthreads();

    const int v0 = bx * 1024 + tid * 4;
    const bool valid = (v0 < VOCAB);
    const unsigned int row_bytes = (unsigned int)(min(1024, VOCAB - bx * 1024)) * 4u;

    unsigned long long w[4][8];
    float bias[4];
    if (valid) {
#pragma unroll
        for (int r = 0; r < 4; r++) {
            const ulonglong2* wp = (const ulonglong2*)(W_ho + (v0 + r) * HID);
            const ulonglong2 wa = wp[0], wb = wp[1], wc = wp[2], wd = wp[3];
            w[r][0] = wa.x; w[r][1] = wa.y; w[r][2] = wb.x; w[r][3] = wb.y;
            w[r][4] = wc.x; w[r][5] = wc.y; w[r][6] = wd.x; w[r][7] = wd.y;
            bias[r] = b_ho[v0 + r];
        }
    } else {
#pragma unroll
        for (int r = 0; r < 4; r++) {
#pragma unroll
            for (int k = 0; k < 8; k++) w[r][k] = 0ull;
            bias[r] = 0.f;
        }
    }

    float* oblk = out + (size_t)s * BATCH * VOCAB + bx * 1024;

    for (int ph = 0; ph < 8; ph++) {
        // ensure buffer (ph&1) has been fully read by the TMA group issued
        // 2 phases ago: allow at most 1 outstanding group.
        if (tid == 0 && ph >= 2)
            asm volatile("cp.async.bulk.wait_group.read 1;" ::: "memory");
        __syncthreads();

        float* buf = &obuf[ph & 1][0][0];
#pragma unroll
        for (int j = 0; j < 4; j++) {
            const int b = ph * 4 + j;
            const ulonglong2 h01 = hs[b][0], h23 = hs[b][1];
            const ulonglong2 h45 = hs[b][2], h67 = hs[b][3];
            const float nl = -lz[b];
            unsigned long long a0 = packf2(bias[0], nl);
            unsigned long long a1 = packf2(bias[1], nl);
            unsigned long long a2 = packf2(bias[2], nl);
            unsigned long long a3 = packf2(bias[3], nl);
            ffma2(a0, w[0][0], h01.x); ffma2(a0, w[0][1], h01.y);
            ffma2(a0, w[0][2], h23.x); ffma2(a0, w[0][3], h23.y);
            ffma2(a0, w[0][4], h45.x); ffma2(a0, w[0][5], h45.y);
            ffma2(a0, w[0][6], h67.x); ffma2(a0, w[0][7], h67.y);
            ffma2(a1, w[1][0], h01.x); ffma2(a1, w[1][1], h01.y);
            ffma2(a1, w[1][2], h23.x); ffma2(a1, w[1][3], h23.y);
            ffma2(a1, w[1][4], h45.x); ffma2(a1, w[1][5], h45.y);
            ffma2(a1, w[1][6], h67.x); ffma2(a1, w[1][7], h67.y);
            ffma2(a2, w[2][0], h01.x); ffma2(a2, w[2][1], h01.y);
            ffma2(a2, w[2][2], h23.x); ffma2(a2, w[2][3], h23.y);
            ffma2(a2, w[2][4], h45.x); ffma2(a2, w[2][5], h45.y);
            ffma2(a2, w[2][6], h67.x); ffma2(a2, w[2][7], h67.y);
            ffma2(a3, w[3][0], h01.x); ffma2(a3, w[3][1], h01.y);
            ffma2(a3, w[3][2], h23.x); ffma2(a3, w[3][3], h23.y);
            ffma2(a3, w[3][4], h45.x); ffma2(a3, w[3][5], h45.y);
            ffma2(a3, w[3][6], h67.x); ffma2(a3, w[3][7], h67.y);
            float4 res;
            res.x = hsum2(a0);
            res.y = hsum2(a1);
            res.z = hsum2(a2);
            res.w = hsum2(a3);
            *(float4*)(buf + j * 1024 + tid * 4) = res;   // STS.128
        }
        __syncthreads();   // slab complete in SMEM

        if (tid == 0) {
            asm volatile("fence.proxy.async.shared::cta;" ::: "memory");
            const unsigned int src0 = smem_u32(buf);
#pragma unroll
            for (int j = 0; j < 4; j++) {
                float* dst = oblk + (size_t)(ph * 4 + j) * VOCAB;
                asm volatile(
                    "cp.async.bulk.global.shared::cta.bulk_group [%0], [%1], %2;"
                    :: "l"(dst), "r"(src0 + j * 4096u), "r"(row_bytes)
                    : "memory");
            }
            asm volatile("cp.async.bulk.commit_group;" ::: "memory");
        }
    }
    // drain all outstanding TMA stores before exit
    if (tid == 0)
        asm volatile("cp.async.bulk.wait_group 0;" ::: "memory");
}

// ---------------------------------------------------------------------------
// Launcher. Input order: input_batch, h0, embedding, W_ih, b_ih, W_ho, b_ho.
// Serial: [prep+recur] -> [p1 HMMA] -> [p2 TMA-store + inline logZ].
// ---------------------------------------------------------------------------
extern "C" void kernel_launch(void* const* d_in, const int* in_sizes, int n_in,
                              void* d_out, int out_size) {
    const int*   idx  = (const int*)  d_in[0];
    const float* h0   = (const float*)d_in[1];
    const float* emb  = (const float*)d_in[2];
    const float* W_ih = (const float*)d_in[3];
    const float* b_ih = (const float*)d_in[4];
    const float* W_ho = (const float*)d_in[5];
    const float* b_ho = (const float*)d_in[6];
    float* out = (float*)d_out;

    recur_prep_kernel<<<PREP_BLOCKS + BATCH, 256>>>(idx, h0, emb, W_ih, b_ih, W_ho, b_ho);
    p1_mma<<<dim3(VSPLIT, SEQ), 256>>>();
    logits_pass2<<<dim3(P2_TILES, SEQ), 256>>>(W_ho, b_ho, out);
}

// round 15
// speedup vs baseline: 1.2797x; 1.2797x over previous
#include <cuda_runtime.h>
#include <cuda_fp16.h>
#include <cstdint>
#include <math.h>
#include <math_constants.h>

#define SEQ   128
#define BATCH 32
#define EMB   32
#define HID   16
#define VOCAB 32000
#define VPAD  32768        // padded vocab (pad rows contribute 0 to sum-exp)
#define CIN   48           // EMB + HID

#define VSPLIT   16        // p1 blocks per timestep (each covers 2048 vocab)
#define P2_TILES 32        // p2 blocks per timestep (each covers 1024 vocab)
#define PREP_BLOCKS 128    // VPAD / 256
#define LOG2E 1.4426950408889634f

// Scratch (no allocations allowed)
__device__ float  g_H[SEQ * BATCH * HID];          // fp32 h for p2
__device__ __half g_Hhf[SEQ * BATCH * HID];        // fp16 h * log2e for p1 MMA
__device__ __half g_Whf[VPAD * HID];               // fp16 W_ho (pad rows = 0)
__device__ float  g_b2[VPAD];                      // b_ho * log2e (pad = -2000)
__device__ float  g_partS[SEQ * VSPLIT * BATCH];

// ---- packed f32x2 helpers ---------------------------------------------------
__device__ __forceinline__ void ffma2(unsigned long long& d,
                                      unsigned long long a,
                                      unsigned long long b) {
    asm("fma.rn.f32x2 %0, %1, %2, %0;" : "+l"(d) : "l"(a), "l"(b));
}
__device__ __forceinline__ unsigned long long add2(unsigned long long a,
                                                   unsigned long long b) {
    unsigned long long d;
    asm("add.rn.f32x2 %0, %1, %2;" : "=l"(d) : "l"(a), "l"(b));
    return d;
}
__device__ __forceinline__ float hsum2(unsigned long long v) {
    float lo, hi;
    asm("mov.b64 {%0, %1}, %2;" : "=f"(lo), "=f"(hi) : "l"(v));
    return lo + hi;
}
__device__ __forceinline__ unsigned long long packf2(float lo, float hi) {
    unsigned long long d;
    asm("mov.b64 %0, {%1, %2};" : "=l"(d) : "f"(lo), "f"(hi));
    return d;
}
__device__ __forceinline__ float ex2(float x) {
    float r;
    asm("ex2.approx.f32 %0, %1;" : "=f"(r) : "f"(x));
    return r;
}
__device__ __forceinline__ float tanh_approx(float x) {
    float r;
    asm("tanh.approx.f32 %0, %1;" : "=f"(r) : "f"(x));
    return r;
}

// mma.sync m16n8k16: D(f32) = A(f16) * B(f16) + C(f32)
__device__ __forceinline__ void mma16816(float& d0, float& d1, float& d2, float& d3,
                                         unsigned a0, unsigned a1, unsigned a2, unsigned a3,
                                         unsigned b0, unsigned b1) {
    const float z = 0.f;
    asm volatile(
        "mma.sync.aligned.m16n8k16.row.col.f32.f16.f16.f32 "
        "{%0,%1,%2,%3}, {%4,%5,%6,%7}, {%8,%9}, {%10,%11,%12,%13};"
        : "=f"(d0), "=f"(d1), "=f"(d2), "=f"(d3)
        : "r"(a0), "r"(a1), "r"(a2), "r"(a3), "r"(b0), "r"(b1),
          "f"(z), "f"(z), "f"(z), "f"(z));
}

// ---------------------------------------------------------------------------
// Kernel A: fused prep + recurrence.
// Recurrence inner: 6x LDS.128 + 12x FFMA2 dot, MUFU.TANH activation.
// ---------------------------------------------------------------------------
__global__ __launch_bounds__(256, 1)
void recur_prep_kernel(const int*   __restrict__ idx,
                       const float* __restrict__ h0,
                       const float* __restrict__ emb,
                       const float* __restrict__ W_ih,
                       const float* __restrict__ b_ih,
                       const float* __restrict__ W_ho,
                       const float* __restrict__ b_ho) {
    if (blockIdx.x < PREP_BLOCKS) {
        const int row = blockIdx.x * 256 + threadIdx.x;
        __half* d = g_Whf + row * HID;
        if (row < VOCAB) {
#pragma unroll
            for (int k = 0; k < HID; k++) d[k] = __float2half(W_ho[row * HID + k]);
            g_b2[row] = b_ho[row] * LOG2E;
        } else {
#pragma unroll
            for (int k = 0; k < HID; k++) d[k] = __float2half(0.f);
            g_b2[row] = -2000.f;
        }
        return;
    }
    if (threadIdx.x >= 32) return;     // recurrence uses one warp

    const int b    = blockIdx.x - PREP_BLOCKS;
    const int lane = threadIdx.x;
    const int i    = lane & 15;
    const int half = lane >> 4;

    __shared__ int idxs[SEQ];
    __shared__ __align__(16) float comb[CIN];

    for (int t = lane; t < SEQ; t += 32) idxs[t] = idx[t * BATCH + b];

    // W_ih row slice [base, base+24) as 12 packed f32x2 (16B-aligned loads)
    unsigned long long wih[12];
    const int base = half * 24;
    {
        const ulonglong2* wp = (const ulonglong2*)(W_ih + i * CIN + base);
#pragma unroll
        for (int q = 0; q < 6; q++) {
            const ulonglong2 v = wp[q];
            wih[q * 2]     = v.x;
            wih[q * 2 + 1] = v.y;
        }
    }
    const float bias = b_ih[i];

    __syncwarp();

    float x = emb[idxs[0] * EMB + lane];
    float h = (lane < 16) ? h0[b * HID + lane] : 0.f;

    for (int t = 0; t < SEQ; t++) {
        comb[lane] = x;
        if (lane < 16) comb[EMB + lane] = h;
        __syncwarp();

        if (t + 1 < SEQ) x = emb[idxs[t + 1] * EMB + lane];

        unsigned long long acc0 = 0ull, acc1 = 0ull, acc2 = 0ull;
        const ulonglong2* cb = (const ulonglong2*)(comb + base);
#pragma unroll
        for (int q = 0; q < 6; q += 3) {
            const ulonglong2 c0 = cb[q], c1 = cb[q + 1], c2 = cb[q + 2];
            ffma2(acc0, wih[q * 2],     c0.x);
            ffma2(acc1, wih[q * 2 + 1], c0.y);
            ffma2(acc2, wih[q * 2 + 2], c1.x);
            ffma2(acc0, wih[q * 2 + 3], c1.y);
            ffma2(acc1, wih[q * 2 + 4], c2.x);
            ffma2(acc2, wih[q * 2 + 5], c2.y);
        }
        float part = hsum2(add2(add2(acc0, acc1), acc2));
        part += __shfl_xor_sync(0xffffffffu, part, 16);

        const float hn = tanh_approx(part + bias);   // MUFU.TANH

        __syncwarp();                 // WAR before next comb writes
        if (lane < 16) {
            h = hn;
            g_H[(t * BATCH + b) * HID + i] = hn;
            g_Hhf[(t * BATCH + b) * HID + i] = __float2half(hn * LOG2E);
        }
    }
}

// ---------------------------------------------------------------------------
// Kernel B (p1 via HMMA): sum-exp of logits on the tensor pipe. Unchanged.
// ---------------------------------------------------------------------------
__global__ __launch_bounds__(256, 4)
void p1_mma() {
    const int s    = blockIdx.y;
    const int bx   = blockIdx.x;
    const int tid  = threadIdx.x;
    const int warp = tid >> 5;
    const int lane = tid & 31;

    __shared__ float rS[8][BATCH];

    const int g  = lane >> 2;
    const int c4 = (lane & 3) * 2;

    const __half* Ah = g_Hhf + s * BATCH * HID;
    const unsigned a0 = *(const unsigned*)(Ah + (g)      * HID + c4);
    const unsigned a1 = *(const unsigned*)(Ah + (g + 8)  * HID + c4);
    const unsigned a2 = *(const unsigned*)(Ah + (g)      * HID + c4 + 8);
    const unsigned a3 = *(const unsigned*)(Ah + (g + 8)  * HID + c4 + 8);
    const unsigned a4 = *(const unsigned*)(Ah + (g + 16) * HID + c4);
    const unsigned a5 = *(const unsigned*)(Ah + (g + 24) * HID + c4);
    const unsigned a6 = *(const unsigned*)(Ah + (g + 16) * HID + c4 + 8);
    const unsigned a7 = *(const unsigned*)(Ah + (g + 24) * HID + c4 + 8);

    float s0 = 0.f, s1 = 0.f, s2 = 0.f, s3 = 0.f;

    const int vwarp = bx * 2048 + warp * 256;
#pragma unroll 4
    for (int tile = 0; tile < 32; tile++) {
        const int v0 = vwarp + tile * 8;
        const __half* Bp = g_Whf + (v0 + g) * HID;
        const unsigned b0 = *(const unsigned*)(Bp + c4);
        const unsigned b1 = *(const unsigned*)(Bp + c4 + 8);
        const float2 bb = *(const float2*)(g_b2 + v0 + c4);

        float d0, d1, d2, d3, e0, e1, e2, e3;
        mma16816(d0, d1, d2, d3, a0, a1, a2, a3, b0, b1);
        mma16816(e0, e1, e2, e3, a4, a5, a6, a7, b0, b1);

        s0 += ex2(d0 + bb.x) + ex2(d1 + bb.y);
        s1 += ex2(d2 + bb.x) + ex2(d3 + bb.y);
        s2 += ex2(e0 + bb.x) + ex2(e1 + bb.y);
        s3 += ex2(e2 + bb.x) + ex2(e3 + bb.y);
    }

    s0 += __shfl_xor_sync(0xffffffffu, s0, 1); s0 += __shfl_xor_sync(0xffffffffu, s0, 2);
    s1 += __shfl_xor_sync(0xffffffffu, s1, 1); s1 += __shfl_xor_sync(0xffffffffu, s1, 2);
    s2 += __shfl_xor_sync(0xffffffffu, s2, 1); s2 += __shfl_xor_sync(0xffffffffu, s2, 2);
    s3 += __shfl_xor_sync(0xffffffffu, s3, 1); s3 += __shfl_xor_sync(0xffffffffu, s3, 2);
    if ((lane & 3) == 0) {
        rS[warp][g]      = s0;
        rS[warp][g + 8]  = s1;
        rS[warp][g + 16] = s2;
        rS[warp][g + 24] = s3;
    }
    __syncthreads();
    if (tid < BATCH) {
        float S = 0.f;
#pragma unroll
        for (int w = 0; w < 8; w++) S += rS[w][tid];
        g_partS[(s * VSPLIT + bx) * BATCH + tid] = S;
    }
}

// ---------------------------------------------------------------------------
// Kernel D (pass 2 + inline logZ): proven 127us config -- 4 vocab/thread,
// fp32 exact recompute, STG.128 streaming stores. DRAM-write-ceiling bound.
// ---------------------------------------------------------------------------
__global__ __launch_bounds__(256, 2)
void logits_pass2(const float* __restrict__ W_ho,
                  const float* __restrict__ b_ho,
                  float* __restrict__ out) {
    const int s   = blockIdx.y;
    const int tid = threadIdx.x;

    __shared__ ulonglong2 hs[BATCH][4];
    __shared__ float      lz[BATCH];
    if (tid < 128)
        ((ulonglong2*)hs)[tid] = ((const ulonglong2*)(g_H + s * BATCH * HID))[tid];
    if (tid < 32) {
        float S = 0.f;
        const float* p = g_partS + s * VSPLIT * BATCH + tid;
#pragma unroll
        for (int t = 0; t < VSPLIT; t++) S += p[t * BATCH];
        lz[tid] = __logf(S);
    }
    __syncthreads();

    const int v0 = (blockIdx.x * 256 + tid) * 4;
    if (v0 >= VOCAB) return;

    unsigned long long w[4][8];
    float bias[4];
#pragma unroll
    for (int r = 0; r < 4; r++) {
        const ulonglong2* wp = (const ulonglong2*)(W_ho + (v0 + r) * HID);
        const ulonglong2 wa = wp[0], wb = wp[1], wc = wp[2], wd = wp[3];
        w[r][0] = wa.x; w[r][1] = wa.y; w[r][2] = wb.x; w[r][3] = wb.y;
        w[r][4] = wc.x; w[r][5] = wc.y; w[r][6] = wd.x; w[r][7] = wd.y;
        bias[r] = b_ho[v0 + r];
    }

    float* orow = out + (size_t)s * BATCH * VOCAB + v0;
#pragma unroll 4
    for (int b = 0; b < BATCH; b++) {
        const ulonglong2 h01 = hs[b][0], h23 = hs[b][1];
        const ulonglong2 h45 = hs[b][2], h67 = hs[b][3];
        const float nl = -lz[b];
        unsigned long long a0 = packf2(bias[0], nl);
        unsigned long long a1 = packf2(bias[1], nl);
        unsigned long long a2 = packf2(bias[2], nl);
        unsigned long long a3 = packf2(bias[3], nl);
        ffma2(a0, w[0][0], h01.x); ffma2(a0, w[0][1], h01.y);
        ffma2(a0, w[0][2], h23.x); ffma2(a0, w[0][3], h23.y);
        ffma2(a0, w[0][4], h45.x); ffma2(a0, w[0][5], h45.y);
        ffma2(a0, w[0][6], h67.x); ffma2(a0, w[0][7], h67.y);
        ffma2(a1, w[1][0], h01.x); ffma2(a1, w[1][1], h01.y);
        ffma2(a1, w[1][2], h23.x); ffma2(a1, w[1][3], h23.y);
        ffma2(a1, w[1][4], h45.x); ffma2(a1, w[1][5], h45.y);
        ffma2(a1, w[1][6], h67.x); ffma2(a1, w[1][7], h67.y);
        ffma2(a2, w[2][0], h01.x); ffma2(a2, w[2][1], h01.y);
        ffma2(a2, w[2][2], h23.x); ffma2(a2, w[2][3], h23.y);
        ffma2(a2, w[2][4], h45.x); ffma2(a2, w[2][5], h45.y);
        ffma2(a2, w[2][6], h67.x); ffma2(a2, w[2][7], h67.y);
        ffma2(a3, w[3][0], h01.x); ffma2(a3, w[3][1], h01.y);
        ffma2(a3, w[3][2], h23.x); ffma2(a3, w[3][3], h23.y);
        ffma2(a3, w[3][4], h45.x); ffma2(a3, w[3][5], h45.y);
        ffma2(a3, w[3][6], h67.x); ffma2(a3, w[3][7], h67.y);
        float4 res;
        res.x = hsum2(a0);
        res.y = hsum2(a1);
        res.z = hsum2(a2);
        res.w = hsum2(a3);
        __stcs((float4*)(orow + (size_t)b * VOCAB), res);
    }
}

// ---------------------------------------------------------------------------
// Launcher. Input order: input_batch, h0, embedding, W_ih, b_ih, W_ho, b_ho.
// Serial: [prep+recur] -> [p1 HMMA] -> [p2 + inline logZ].
// ---------------------------------------------------------------------------
extern "C" void kernel_launch(void* const* d_in, const int* in_sizes, int n_in,
                              void* d_out, int out_size) {
    const int*   idx  = (const int*)  d_in[0];
    const float* h0   = (const float*)d_in[1];
    const float* emb  = (const float*)d_in[2];
    const float* W_ih = (const float*)d_in[3];
    const float* b_ih = (const float*)d_in[4];
    const float* W_ho = (const float*)d_in[5];
    const float* b_ho = (const float*)d_in[6];
    float* out = (float*)d_out;

    recur_prep_kernel<<<PREP_BLOCKS + BATCH, 256>>>(idx, h0, emb, W_ih, b_ih, W_ho, b_ho);
    p1_mma<<<dim3(VSPLIT, SEQ), 256>>>();
    logits_pass2<<<dim3(P2_TILES, SEQ), 256>>>(W_ho, b_ho, out);
}

// round 16
// speedup vs baseline: 1.3632x; 1.0653x over previous
#include <cuda_runtime.h>
#include <cuda_fp16.h>
#include <cstdint>
#include <math.h>
#include <math_constants.h>

#define SEQ   128
#define BATCH 32
#define EMB   32
#define HID   16
#define VOCAB 32000
#define VPAD  32768        // padded vocab (pad rows contribute 0 to sum-exp)
#define CIN   48           // EMB + HID

#define VSPLIT   16        // p1 blocks per timestep (each covers 2048 vocab)
#define P2_TILES 32        // p2 blocks per timestep (each covers 1024 vocab)
#define PREP_BLOCKS 128    // VPAD / 256
#define LOG2E 1.4426950408889634f

// Scratch (no allocations allowed)
__device__ float  g_H[SEQ * BATCH * HID];          // fp32 h for p2
__device__ __half g_Hhf[SEQ * BATCH * HID];        // fp16 h * log2e for p1 MMA
__device__ __half g_Whf[VPAD * HID];               // fp16 W_ho (pad rows = 0)
__device__ float  g_b2[VPAD];                      // b_ho * log2e (pad = -2000)
__device__ float  g_partS[SEQ * VSPLIT * BATCH];

// ---- packed f32x2 helpers ---------------------------------------------------
__device__ __forceinline__ void ffma2(unsigned long long& d,
                                      unsigned long long a,
                                      unsigned long long b) {
    asm("fma.rn.f32x2 %0, %1, %2, %0;" : "+l"(d) : "l"(a), "l"(b));
}
__device__ __forceinline__ float hsum2(unsigned long long v) {
    float lo, hi;
    asm("mov.b64 {%0, %1}, %2;" : "=f"(lo), "=f"(hi) : "l"(v));
    return lo + hi;
}
__device__ __forceinline__ unsigned long long packf2(float lo, float hi) {
    unsigned long long d;
    asm("mov.b64 %0, {%1, %2};" : "=l"(d) : "f"(lo), "f"(hi));
    return d;
}
__device__ __forceinline__ float ex2(float x) {
    float r;
    asm("ex2.approx.f32 %0, %1;" : "=f"(r) : "f"(x));
    return r;
}
// pack two fp32 into f16x2 (lo = a, hi = b), one CVT op
__device__ __forceinline__ unsigned pack_h2(float a, float b) {
    unsigned r;
    asm("cvt.rn.f16x2.f32 %0, %1, %2;" : "=r"(r) : "f"(b), "f"(a));
    return r;
}
// dual exp2 on packed f16x2, one MUFU op
__device__ __forceinline__ unsigned ex2_h2(unsigned x) {
    unsigned r;
    asm("ex2.approx.f16x2 %0, %1;" : "=r"(r) : "r"(x));
    return r;
}
// unpack f16x2 and sum both halves into an fp32 accumulator
__device__ __forceinline__ void acc_h2(float& s, unsigned x) {
    const __half2 h = *reinterpret_cast<const __half2*>(&x);
    const float2 f = __half22float2(h);
    s += f.x + f.y;
}

// mma.sync m16n8k16 with bias in C: D = A*B + C
__device__ __forceinline__ void mma16816c(float& d0, float& d1, float& d2, float& d3,
                                          unsigned a0, unsigned a1, unsigned a2, unsigned a3,
                                          unsigned b0, unsigned b1,
                                          float cx, float cy) {
    asm volatile(
        "mma.sync.aligned.m16n8k16.row.col.f32.f16.f16.f32 "
        "{%0,%1,%2,%3}, {%4,%5,%6,%7}, {%8,%9}, {%10,%11,%10,%11};"
        : "=f"(d0), "=f"(d1), "=f"(d2), "=f"(d3)
        : "r"(a0), "r"(a1), "r"(a2), "r"(a3), "r"(b0), "r"(b1),
          "f"(cx), "f"(cy));
}

// ---------------------------------------------------------------------------
// Kernel A: fused prep + recurrence (recurrence = proven scalar form).
// ---------------------------------------------------------------------------
__global__ __launch_bounds__(256, 1)
void recur_prep_kernel(const int*   __restrict__ idx,
                       const float* __restrict__ h0,
                       const float* __restrict__ emb,
                       const float* __restrict__ W_ih,
                       const float* __restrict__ b_ih,
                       const float* __restrict__ W_ho,
                       const float* __restrict__ b_ho) {
    if (blockIdx.x < PREP_BLOCKS) {
        const int row = blockIdx.x * 256 + threadIdx.x;
        __half* d = g_Whf + row * HID;
        if (row < VOCAB) {
#pragma unroll
            for (int k = 0; k < HID; k++) d[k] = __float2half(W_ho[row * HID + k]);
            g_b2[row] = b_ho[row] * LOG2E;
        } else {
#pragma unroll
            for (int k = 0; k < HID; k++) d[k] = __float2half(0.f);
            g_b2[row] = -2000.f;
        }
        return;
    }
    if (threadIdx.x >= 32) return;     // recurrence uses one warp

    const int b    = blockIdx.x - PREP_BLOCKS;
    const int lane = threadIdx.x;
    const int i    = lane & 15;
    const int half = lane >> 4;

    __shared__ int   idxs[SEQ];
    __shared__ float comb[CIN];

    for (int t = lane; t < SEQ; t += 32) idxs[t] = idx[t * BATCH + b];

    float wih[24];
    const int base = half * 24;
#pragma unroll
    for (int j = 0; j < 24; j++) wih[j] = W_ih[i * CIN + base + j];
    const float bias = b_ih[i];

    __syncwarp();

    float x = emb[idxs[0] * EMB + lane];
    float h = (lane < 16) ? h0[b * HID + lane] : 0.f;

    for (int t = 0; t < SEQ; t++) {
        comb[lane] = x;
        if (lane < 16) comb[EMB + lane] = h;
        __syncwarp();

        if (t + 1 < SEQ) x = emb[idxs[t + 1] * EMB + lane];

        float a0 = 0.f, a1 = 0.f, a2 = 0.f;
#pragma unroll
        for (int j = 0; j < 24; j += 3) {
            a0 += wih[j]     * comb[base + j];
            a1 += wih[j + 1] * comb[base + j + 1];
            a2 += wih[j + 2] * comb[base + j + 2];
        }
        float part = (a0 + a1) + a2;
        part += __shfl_xor_sync(0xffffffffu, part, 16);

        const float z = part + bias;
        const float e = ex2(2.f * LOG2E * z);
        const float hn = __fdividef(e - 1.f, e + 1.f);

        __syncwarp();
        if (lane < 16) {
            h = hn;
            g_H[(t * BATCH + b) * HID + i] = hn;
            g_Hhf[(t * BATCH + b) * HID + i] = __float2half(hn * LOG2E);
        }
    }
}

// ---------------------------------------------------------------------------
// Kernel B (p1 via HMMA): sum-exp on tensor pipe; bias folded into MMA C;
// exps evaluated 2-at-a-time via ex2.approx.f16x2 (halves MUFU demand).
// ---------------------------------------------------------------------------
__global__ __launch_bounds__(256, 4)
void p1_mma() {
    const int s    = blockIdx.y;
    const int bx   = blockIdx.x;
    const int tid  = threadIdx.x;
    const int warp = tid >> 5;
    const int lane = tid & 31;

    __shared__ float rS[8][BATCH];

    const int g  = lane >> 2;
    const int c4 = (lane & 3) * 2;

    const __half* Ah = g_Hhf + s * BATCH * HID;
    const unsigned a0 = *(const unsigned*)(Ah + (g)      * HID + c4);
    const unsigned a1 = *(const unsigned*)(Ah + (g + 8)  * HID + c4);
    const unsigned a2 = *(const unsigned*)(Ah + (g)      * HID + c4 + 8);
    const unsigned a3 = *(const unsigned*)(Ah + (g + 8)  * HID + c4 + 8);
    const unsigned a4 = *(const unsigned*)(Ah + (g + 16) * HID + c4);
    const unsigned a5 = *(const unsigned*)(Ah + (g + 24) * HID + c4);
    const unsigned a6 = *(const unsigned*)(Ah + (g + 16) * HID + c4 + 8);
    const unsigned a7 = *(const unsigned*)(Ah + (g + 24) * HID + c4 + 8);

    float s0 = 0.f, s1 = 0.f, s2 = 0.f, s3 = 0.f;

    const int vwarp = bx * 2048 + warp * 256;
#pragma unroll 4
    for (int tile = 0; tile < 32; tile++) {
        const int v0 = vwarp + tile * 8;
        const __half* Bp = g_Whf + (v0 + g) * HID;
        const unsigned b0 = *(const unsigned*)(Bp + c4);
        const unsigned b1 = *(const unsigned*)(Bp + c4 + 8);
        const float2 bb = *(const float2*)(g_b2 + v0 + c4);

        float d0, d1, d2, d3, e0, e1, e2, e3;
        mma16816c(d0, d1, d2, d3, a0, a1, a2, a3, b0, b1, bb.x, bb.y);
        mma16816c(e0, e1, e2, e3, a4, a5, a6, a7, b0, b1, bb.x, bb.y);

        acc_h2(s0, ex2_h2(pack_h2(d0, d1)));   // batch g
        acc_h2(s1, ex2_h2(pack_h2(d2, d3)));   // batch g+8
        acc_h2(s2, ex2_h2(pack_h2(e0, e1)));   // batch g+16
        acc_h2(s3, ex2_h2(pack_h2(e2, e3)));   // batch g+24
    }

    s0 += __shfl_xor_sync(0xffffffffu, s0, 1); s0 += __shfl_xor_sync(0xffffffffu, s0, 2);
    s1 += __shfl_xor_sync(0xffffffffu, s1, 1); s1 += __shfl_xor_sync(0xffffffffu, s1, 2);
    s2 += __shfl_xor_sync(0xffffffffu, s2, 1); s2 += __shfl_xor_sync(0xffffffffu, s2, 2);
    s3 += __shfl_xor_sync(0xffffffffu, s3, 1); s3 += __shfl_xor_sync(0xffffffffu, s3, 2);
    if ((lane & 3) == 0) {
        rS[warp][g]      = s0;
        rS[warp][g + 8]  = s1;
        rS[warp][g + 16] = s2;
        rS[warp][g + 24] = s3;
    }
    __syncthreads();
    if (tid < BATCH) {
        float S = 0.f;
#pragma unroll
        for (int w = 0; w < 8; w++) S += rS[w][tid];
        g_partS[(s * VSPLIT + bx) * BATCH + tid] = S;
    }
}

// ---------------------------------------------------------------------------
// Kernel D (pass 2 + inline logZ): proven 127us config. Unchanged.
// ---------------------------------------------------------------------------
__global__ __launch_bounds__(256, 2)
void logits_pass2(const float* __restrict__ W_ho,
                  const float* __restrict__ b_ho,
                  float* __restrict__ out) {
    const int s   = blockIdx.y;
    const int tid = threadIdx.x;

    __shared__ ulonglong2 hs[BATCH][4];
    __shared__ float      lz[BATCH];
    if (tid < 128)
        ((ulonglong2*)hs)[tid] = ((const ulonglong2*)(g_H + s * BATCH * HID))[tid];
    if (tid < 32) {
        float S = 0.f;
        const float* p = g_partS + s * VSPLIT * BATCH + tid;
#pragma unroll
        for (int t = 0; t < VSPLIT; t++) S += p[t * BATCH];
        lz[tid] = __logf(S);
    }
    __syncthreads();

    const int v0 = (blockIdx.x * 256 + tid) * 4;
    if (v0 >= VOCAB) return;

    unsigned long long w[4][8];
    float bias[4];
#pragma unroll
    for (int r = 0; r < 4; r++) {
        const ulonglong2* wp = (const ulonglong2*)(W_ho + (v0 + r) * HID);
        const ulonglong2 wa = wp[0], wb = wp[1], wc = wp[2], wd = wp[3];
        w[r][0] = wa.x; w[r][1] = wa.y; w[r][2] = wb.x; w[r][3] = wb.y;
        w[r][4] = wc.x; w[r][5] = wc.y; w[r][6] = wd.x; w[r][7] = wd.y;
        bias[r] = b_ho[v0 + r];
    }

    float* orow = out + (size_t)s * BATCH * VOCAB + v0;
#pragma unroll 4
    for (int b = 0; b < BATCH; b++) {
        const ulonglong2 h01 = hs[b][0], h23 = hs[b][1];
        const ulonglong2 h45 = hs[b][2], h67 = hs[b][3];
        const float nl = -lz[b];
        unsigned long long a0 = packf2(bias[0], nl);
        unsigned long long a1 = packf2(bias[1], nl);
        unsigned long long a2 = packf2(bias[2], nl);
        unsigned long long a3 = packf2(bias[3], nl);
        ffma2(a0, w[0][0], h01.x); ffma2(a0, w[0][1], h01.y);
        ffma2(a0, w[0][2], h23.x); ffma2(a0, w[0][3], h23.y);
        ffma2(a0, w[0][4], h45.x); ffma2(a0, w[0][5], h45.y);
        ffma2(a0, w[0][6], h67.x); ffma2(a0, w[0][7], h67.y);
        ffma2(a1, w[1][0], h01.x); ffma2(a1, w[1][1], h01.y);
        ffma2(a1, w[1][2], h23.x); ffma2(a1, w[1][3], h23.y);
        ffma2(a1, w[1][4], h45.x); ffma2(a1, w[1][5], h45.y);
        ffma2(a1, w[1][6], h67.x); ffma2(a1, w[1][7], h67.y);
        ffma2(a2, w[2][0], h01.x); ffma2(a2, w[2][1], h01.y);
        ffma2(a2, w[2][2], h23.x); ffma2(a2, w[2][3], h23.y);
        ffma2(a2, w[2][4], h45.x); ffma2(a2, w[2][5], h45.y);
        ffma2(a2, w[2][6], h67.x); ffma2(a2, w[2][7], h67.y);
        ffma2(a3, w[3][0], h01.x); ffma2(a3, w[3][1], h01.y);
        ffma2(a3, w[3][2], h23.x); ffma2(a3, w[3][3], h23.y);
        ffma2(a3, w[3][4], h45.x); ffma2(a3, w[3][5], h45.y);
        ffma2(a3, w[3][6], h67.x); ffma2(a3, w[3][7], h67.y);
        float4 res;
        res.x = hsum2(a0);
        res.y = hsum2(a1);
        res.z = hsum2(a2);
        res.w = hsum2(a3);
        __stcs((float4*)(orow + (size_t)b * VOCAB), res);
    }
}

// ---------------------------------------------------------------------------
// Launcher. Input order: input_batch, h0, embedding, W_ih, b_ih, W_ho, b_ho.
// Serial: [prep+recur] -> [p1 HMMA] -> [p2 + inline logZ].
// ---------------------------------------------------------------------------
extern "C" void kernel_launch(void* const* d_in, const int* in_sizes, int n_in,
                              void* d_out, int out_size) {
    const int*   idx  = (const int*)  d_in[0];
    const float* h0   = (const float*)d_in[1];
    const float* emb  = (const float*)d_in[2];
    const float* W_ih = (const float*)d_in[3];
    const float* b_ih = (const float*)d_in[4];
    const float* W_ho = (const float*)d_in[5];
    const float* b_ho = (const float*)d_in[6];
    float* out = (float*)d_out;

    recur_prep_kernel<<<PREP_BLOCKS + BATCH, 256>>>(idx, h0, emb, W_ih, b_ih, W_ho, b_ho);
    p1_mma<<<dim3(VSPLIT, SEQ), 256>>>();
    logits_pass2<<<dim3(P2_TILES, SEQ), 256>>>(W_ho, b_ho, out);
}